// round 15
// baseline (speedup 1.0000x reference)
#include <cuda_runtime.h>
#include <mma.h>
#include <math.h>
#include <stdint.h>
#include <cstdint>

using namespace nvcuda;

#define BB 64
#define TT 256
#define DD 512
#define HH 1024
#define G4 4096
#define OO 512
#define NBLK 128
#define REC_THR 256
#define MROWS (BB*TT)   // 16384

// ---------------- scratch (device globals: allocation-free rule) -----------
__device__ float g_xz[(size_t)MROWS * G4];     // 256 MB
__device__ float g_seq1[(size_t)MROWS * HH];   // 64 MB, [t][b][h]
__device__ float g_Wt[(size_t)HH * G4];        // tf32-truncated W
__device__ float g_hA[BB * HH];
__device__ float g_hB[BB * HH];
__device__ unsigned g_count = 0;
__device__ volatile unsigned g_gen = 0;

__device__ __forceinline__ float to_tf32(float x) {
    float r; asm("cvt.rna.tf32.f32 %0, %1;" : "=f"(r) : "f"(x)); return r;
}
__device__ __forceinline__ uint32_t smem_u32(const void* p) {
    uint32_t a;
    asm("{ .reg .u64 t; cvta.to.shared.u64 t, %1; cvt.u32.u64 %0, t; }"
        : "=r"(a) : "l"(p));
    return a;
}

// raw tf32 mma m16n8k8
__device__ __forceinline__ void mma_tf32(float* c,
    float a0, float a1, float a2, float a3, float b0, float b1)
{
    asm volatile(
        "mma.sync.aligned.m16n8k8.row.col.f32.tf32.tf32.f32 "
        "{%0,%1,%2,%3}, {%4,%5,%6,%7}, {%8,%9}, {%0,%1,%2,%3};"
        : "+f"(c[0]), "+f"(c[1]), "+f"(c[2]), "+f"(c[3])
        : "r"(__float_as_uint(a0)), "r"(__float_as_uint(a1)),
          "r"(__float_as_uint(a2)), "r"(__float_as_uint(a3)),
          "r"(__float_as_uint(b0)), "r"(__float_as_uint(b1)));
}

// lstm_rec smem: 2 h-chunk buffers [64][260] + zs [8][64][40]
#define BUF_FLOATS 16640
#define ZS_STRIDE  40
#define ZS_OFF     (2 * BUF_FLOATS)
#define REC_SMEM_BYTES ((ZS_OFF + 8 * 64 * ZS_STRIDE) * 4)   // 215040

// ---------------- full software grid barrier (init only) -------------------
__device__ __forceinline__ void grid_barrier() {
    __syncthreads();
    if (threadIdx.x == 0) {
        __threadfence();
        unsigned gen = g_gen;
        if (atomicAdd(&g_count, 1u) == NBLK - 1u) {
            g_count = 0u;
            __threadfence();
            g_gen = gen + 1u;
        } else {
            while (g_gen == gen) {}
        }
        __threadfence();
    }
    __syncthreads();
}

// ---------------- tf32 pre-truncation of weights (input GEMM B) ------------
__global__ void trunc_kernel(const float* __restrict__ in,
                             float* __restrict__ out, int n4)
{
    int i = blockIdx.x * blockDim.x + threadIdx.x;
    if (i < n4) {
        float4 v = ((const float4*)in)[i];
        v.x = to_tf32(v.x); v.y = to_tf32(v.y);
        v.z = to_tf32(v.z); v.w = to_tf32(v.w);
        ((float4*)out)[i] = v;
    }
}

// ---------------------------------------------------------------------------
// Input GEMM v4: C[r][n] = A[r][:] @ Bt[:][n]
// Block tile 128x128, BK=16, double-buffered smem (static 37 KB),
// 512 threads = 16 warps (4x4), warp tile 32x32 (2x2 m16n16k8 tf32 frags).
// A truncated to tf32 during staging; Bt pre-truncated.
// REMAP=1: output row r=(t*64+b) <- A row (b*256+t).
// ---------------------------------------------------------------------------
template<int REMAP>
__global__ __launch_bounds__(512) void input_gemm(
    const float* __restrict__ A, const float* __restrict__ Bt,
    float* __restrict__ C, int K)
{
    __shared__ __align__(16) float As[2][128][20];
    __shared__ __align__(16) float Bs[2][16][132];
    const int tid = threadIdx.x;
    const int wid = tid >> 5;
    const int wr = wid >> 2;        // 0..3  (32-row band)
    const int wc = wid & 3;         // 0..3  (32-col band)
    const int r0 = blockIdx.y * 128, n0 = blockIdx.x * 128;

    wmma::fragment<wmma::accumulator, 16, 16, 8, float> c[2][2];
#pragma unroll
    for (int i = 0; i < 2; i++)
#pragma unroll
        for (int j = 0; j < 2; j++) wmma::fill_fragment(c[i][j], 0.f);

    // A staging: 128 rows x 16 k, one float4 per thread
    const int arow = tid >> 2, ak4 = (tid & 3) * 4;
    const int rr = r0 + arow;
    const size_t gr = REMAP ? ((size_t)(rr & 63) * TT + (rr >> 6)) : (size_t)rr;
    const float* aptr = A + gr * K + ak4;
    // B staging: 16 k-rows x 128 cols, one float4 per thread
    const int brow = tid >> 5, bc4 = (tid & 31) * 4;
    const float* bptr = Bt + (size_t)brow * G4 + n0 + bc4;

    float4 av, bv;

#define LOADK(kc)                                                   \
    do {                                                            \
        av = *(const float4*)(aptr + (kc));                         \
        bv = *(const float4*)(bptr + (size_t)(kc) * G4);            \
    } while (0)

#define STOREK(s)                                                   \
    do {                                                            \
        As[s][arow][ak4 + 0] = to_tf32(av.x);                       \
        As[s][arow][ak4 + 1] = to_tf32(av.y);                       \
        As[s][arow][ak4 + 2] = to_tf32(av.z);                       \
        As[s][arow][ak4 + 3] = to_tf32(av.w);                       \
        *(float4*)&Bs[s][brow][bc4] = bv;                           \
    } while (0)

    LOADK(0);
    STOREK(0);
    __syncthreads();

    int s = 0;
    for (int kc = 0; kc < K; kc += 16) {
        const int nxt = kc + 16;
        if (nxt < K) LOADK(nxt);
#pragma unroll
        for (int kk = 0; kk < 2; kk++) {
            wmma::fragment<wmma::matrix_a, 16, 16, 8, wmma::precision::tf32, wmma::row_major> af[2];
            wmma::fragment<wmma::matrix_b, 16, 16, 8, wmma::precision::tf32, wmma::row_major> bf[2];
#pragma unroll
            for (int i = 0; i < 2; i++)
                wmma::load_matrix_sync(af[i], &As[s][wr * 32 + i * 16][kk * 8], 20);
#pragma unroll
            for (int j = 0; j < 2; j++)
                wmma::load_matrix_sync(bf[j], &Bs[s][kk * 8][wc * 32 + j * 16], 132);
#pragma unroll
            for (int i = 0; i < 2; i++)
#pragma unroll
                for (int j = 0; j < 2; j++)
                    wmma::mma_sync(c[i][j], af[i], bf[j], c[i][j]);
        }
        if (nxt < K) STOREK(s ^ 1);
        s ^= 1;
        __syncthreads();
    }
#undef LOADK
#undef STOREK

#pragma unroll
    for (int i = 0; i < 2; i++)
#pragma unroll
        for (int j = 0; j < 2; j++)
            wmma::store_matrix_sync(
                C + (size_t)(r0 + wr * 32 + i * 16) * G4 + n0 + wc * 32 + j * 16,
                c[i][j], G4, wmma::mem_row_major);
}

// ---------------------------------------------------------------------------
// Persistent recurrent layer (exact round-13 version).
// ---------------------------------------------------------------------------
template<bool WRITE_SEQ>
__global__ __launch_bounds__(REC_THR, 1) void lstm_rec(
    const float* __restrict__ xz,
    const float* __restrict__ U,
    const float* __restrict__ bias,
    float* __restrict__ seq_out)
{
    extern __shared__ __align__(16) float smem[];
    float* zsb = smem + ZS_OFF;

    const int tid  = threadIdx.x;
    const int w    = tid >> 5;
    const int lane = tid & 31;
    const int u0   = blockIdx.x * 8;
    const int lq   = lane >> 2;
    const int lr   = lane & 3;

    float breg[128];
#pragma unroll
    for (int c = 0; c < 4; c++)
#pragma unroll
        for (int q = 0; q < 4; q++)
#pragma unroll
            for (int j = 0; j < 4; j++)
#pragma unroll
                for (int r = 0; r < 2; r++) {
                    int kg = c * 256 + w * 32 + q * 8 + r * 4 + lr;
                    breg[((c * 4 + q) * 4 + j) * 2 + r] =
                        to_tf32(__ldg(&U[(size_t)kg * G4 + j * HH + u0 + lq]));
                }

    float creg[2] = {0.f, 0.f};
    float bg[2][4], xzv[2][4];
#pragma unroll
    for (int i = 0; i < 2; i++) {
        int p = tid + i * 256;
        int b = p >> 3, uu = p & 7;
        g_hA[b * HH + u0 + uu] = 0.f;
#pragma unroll
        for (int g = 0; g < 4; g++) {
            bg[i][g]  = __ldg(&bias[g * HH + u0 + uu]);
            xzv[i][g] = __ldcg(&xz[(size_t)b * G4 + g * HH + u0 + uu]);
        }
    }
    grid_barrier();

    const uint32_t sb0 = smem_u32(smem);

    for (int t = 0; t < TT; t++) {
        const float* hp = (t & 1) ? g_hB : g_hA;
        float*       hn = (t & 1) ? g_hA : g_hB;

        float C[4][4][4];
#pragma unroll
        for (int m = 0; m < 4; m++)
#pragma unroll
            for (int j = 0; j < 4; j++)
#pragma unroll
                for (int r = 0; r < 4; r++) C[m][j][r] = 0.f;

#define CP_ISSUE(cc)                                                          \
        do {                                                                  \
            uint32_t dbase = sb0 + ((cc) & 1) * (BUF_FLOATS * 4);             \
            _Pragma("unroll")                                                 \
            for (int it = 0; it < 16; it++) {                                 \
                int idx = tid + it * 256;                                     \
                int row = idx >> 6, qq = idx & 63;                            \
                uint32_t d = dbase + (uint32_t)(row * 260 + qq * 4) * 4;      \
                const float* sgp = hp + (size_t)row * HH + (cc) * 256 + qq * 4; \
                asm volatile("cp.async.cg.shared.global [%0], [%1], 16;"      \
                             :: "r"(d), "l"(sgp));                            \
            }                                                                 \
            asm volatile("cp.async.commit_group;" ::: "memory");              \
        } while (0)

        CP_ISSUE(0);
        CP_ISSUE(1);

#pragma unroll
        for (int c = 0; c < 4; c++) {
            if (c < 3) asm volatile("cp.async.wait_group 1;" ::: "memory");
            else       asm volatile("cp.async.wait_group 0;" ::: "memory");
            __syncthreads();
            const float* bufc = smem + (c & 1) * BUF_FLOATS;
#pragma unroll
            for (int q = 0; q < 4; q++) {
                const int kb = w * 32 + q * 8 + lr;
#pragma unroll
                for (int m = 0; m < 4; m++) {
                    const int r0 = m * 16 + lq;
                    float a0 = bufc[r0 * 260 + kb];
                    float a1 = bufc[(r0 + 8) * 260 + kb];
                    float a2 = bufc[r0 * 260 + kb + 4];
                    float a3 = bufc[(r0 + 8) * 260 + kb + 4];
#pragma unroll
                    for (int j = 0; j < 4; j++)
                        mma_tf32(C[m][j], a0, a1, a2, a3,
                                 breg[((c * 4 + q) * 4 + j) * 2],
                                 breg[((c * 4 + q) * 4 + j) * 2 + 1]);
                }
            }
            if (c < 2) {
                __syncthreads();
                CP_ISSUE(c + 2);
            }
        }
#undef CP_ISSUE

        {
            float* zp = zsb + w * (64 * ZS_STRIDE);
#pragma unroll
            for (int m = 0; m < 4; m++) {
                int r0 = m * 16 + lq;
#pragma unroll
                for (int j = 0; j < 4; j++) {
                    int col = j * 8 + lr * 2;
                    *(float2*)&zp[r0 * ZS_STRIDE + col] =
                        make_float2(C[m][j][0], C[m][j][1]);
                    *(float2*)&zp[(r0 + 8) * ZS_STRIDE + col] =
                        make_float2(C[m][j][2], C[m][j][3]);
                }
            }
        }
        __syncthreads();

#pragma unroll
        for (int i = 0; i < 2; i++) {
            int p = tid + i * 256;
            int b = p >> 3, uu = p & 7;
            float z[4];
#pragma unroll
            for (int g = 0; g < 4; g++) {
                float v = xzv[i][g] + bg[i][g];
#pragma unroll
                for (int pw = 0; pw < 8; pw++)
                    v += zsb[pw * (64 * ZS_STRIDE) + b * ZS_STRIDE + g * 8 + uu];
                z[g] = v;
            }
            float ig = 1.f / (1.f + __expf(-z[0]));
            float fg = 1.f / (1.f + __expf(-z[1]));
            float og = 1.f / (1.f + __expf(-z[3]));
            float cn = fg * creg[i] + ig * tanhf(z[2]);
            float hv = og * tanhf(cn);
            creg[i] = cn;
            hn[b * HH + u0 + uu] = to_tf32(hv);
            if (WRITE_SEQ)
                seq_out[((size_t)t * BB + b) * HH + u0 + uu] = hv;
        }

        __syncthreads();
        unsigned gn0 = 0;
        if (tid == 0) {
            __threadfence();
            gn0 = g_gen;
            if (atomicAdd(&g_count, 1u) == NBLK - 1u) {
                g_count = 0u;
                __threadfence();
                g_gen = gn0 + 1u;
            }
        }
        if (t + 1 < TT) {
#pragma unroll
            for (int i = 0; i < 2; i++) {
                int p = tid + i * 256;
                int b = p >> 3, uu = p & 7;
                const float* xzr = xz + ((size_t)(t + 1) * BB + b) * G4;
#pragma unroll
                for (int g = 0; g < 4; g++)
                    xzv[i][g] = __ldcg(&xzr[g * HH + u0 + uu]);
            }
        }
        if (tid == 0) {
            while (g_gen == gn0) {}
            __threadfence();
        }
        __syncthreads();
    }
}

// ---------------------------------------------------------------------------
__global__ __launch_bounds__(OO) void dense_kernel(
    const float* __restrict__ Wd, const float* __restrict__ bd,
    float* __restrict__ out)
{
    __shared__ float hs[HH];
    int b = blockIdx.x;
    int o = threadIdx.x;
    for (int k = o; k < HH; k += OO) hs[k] = g_hA[(size_t)b * HH + k];
    __syncthreads();
    float acc = 0.f;
#pragma unroll 8
    for (int k = 0; k < HH; k++)
        acc += hs[k] * __ldg(&Wd[(size_t)k * OO + o]);
    out[(size_t)b * OO + o] = acc + bd[o];
}

// ---------------------------------------------------------------------------
extern "C" void kernel_launch(void* const* d_in, const int* in_sizes, int n_in,
                              void* d_out, int out_size)
{
    const float* x  = (const float*)d_in[0];
    const float* W1 = (const float*)d_in[1];
    const float* U1 = (const float*)d_in[2];
    const float* b1 = (const float*)d_in[3];
    const float* W2 = (const float*)d_in[4];
    const float* U2 = (const float*)d_in[5];
    const float* b2 = (const float*)d_in[6];
    const float* Wd = (const float*)d_in[7];
    const float* bd = (const float*)d_in[8];
    float* out = (float*)d_out;

    float *xz, *seq1, *Wt;
    cudaGetSymbolAddress((void**)&xz,   g_xz);
    cudaGetSymbolAddress((void**)&seq1, g_seq1);
    cudaGetSymbolAddress((void**)&Wt,   g_Wt);

    cudaFuncSetAttribute(lstm_rec<true>,
        cudaFuncAttributeMaxDynamicSharedMemorySize, REC_SMEM_BYTES);
    cudaFuncSetAttribute(lstm_rec<false>,
        cudaFuncAttributeMaxDynamicSharedMemorySize, REC_SMEM_BYTES);

    // ---- layer 1 ----
    trunc_kernel<<<(DD * G4 / 4 + 255) / 256, 256>>>(W1, Wt, DD * G4 / 4);
    input_gemm<1><<<dim3(G4 / 128, MROWS / 128), 512>>>(x, Wt, xz, DD);
    lstm_rec<true><<<NBLK, REC_THR, REC_SMEM_BYTES>>>(xz, U1, b1, seq1);

    // ---- layer 2 ----
    trunc_kernel<<<(HH * G4 / 4 + 255) / 256, 256>>>(W2, Wt, HH * G4 / 4);
    input_gemm<0><<<dim3(G4 / 128, MROWS / 128), 512>>>(seq1, Wt, xz, HH);
    lstm_rec<false><<<NBLK, REC_THR, REC_SMEM_BYTES>>>(xz, U2, b2, nullptr);

    // ---- dense head ----
    dense_kernel<<<BB, OO>>>(Wd, bd, out);
}

// round 16
// speedup vs baseline: 1.1420x; 1.1420x over previous
#include <cuda_runtime.h>
#include <mma.h>
#include <math.h>
#include <stdint.h>
#include <cstdint>

using namespace nvcuda;

#define BB 64
#define TT 256
#define DD 512
#define HH 1024
#define G4 4096
#define OO 512
#define NBLK 128
#define REC_THR 256
#define MROWS (BB*TT)   // 16384

// ---------------- scratch (device globals: allocation-free rule) -----------
__device__ float g_xz[(size_t)MROWS * G4];     // 256 MB
__device__ float g_seq1[(size_t)MROWS * HH];   // 64 MB; trunc(x) early, seq later
__device__ float g_Wt[(size_t)HH * G4];        // tf32-truncated W
__device__ float g_hA[BB * HH];
__device__ float g_hB[BB * HH];
__device__ unsigned g_count = 0;
__device__ volatile unsigned g_gen = 0;

__device__ __forceinline__ float to_tf32(float x) {
    float r; asm("cvt.rna.tf32.f32 %0, %1;" : "=f"(r) : "f"(x)); return r;
}
__device__ __forceinline__ uint32_t smem_u32(const void* p) {
    uint32_t a;
    asm("{ .reg .u64 t; cvta.to.shared.u64 t, %1; cvt.u32.u64 %0, t; }"
        : "=r"(a) : "l"(p));
    return a;
}

// raw tf32 mma m16n8k8
__device__ __forceinline__ void mma_tf32(float* c,
    float a0, float a1, float a2, float a3, float b0, float b1)
{
    asm volatile(
        "mma.sync.aligned.m16n8k8.row.col.f32.tf32.tf32.f32 "
        "{%0,%1,%2,%3}, {%4,%5,%6,%7}, {%8,%9}, {%0,%1,%2,%3};"
        : "+f"(c[0]), "+f"(c[1]), "+f"(c[2]), "+f"(c[3])
        : "r"(__float_as_uint(a0)), "r"(__float_as_uint(a1)),
          "r"(__float_as_uint(a2)), "r"(__float_as_uint(a3)),
          "r"(__float_as_uint(b0)), "r"(__float_as_uint(b1)));
}

// lstm_rec smem: 2 h-chunk buffers [64][260] + zs [8][64][40]
#define BUF_FLOATS 16640
#define ZS_STRIDE  40
#define ZS_OFF     (2 * BUF_FLOATS)
#define REC_SMEM_BYTES ((ZS_OFF + 8 * 64 * ZS_STRIDE) * 4)   // 215040

// input_gemm v5 smem: 3 stages of (A 128x20 + B 16x132)
#define IGA_STRIDE 20
#define IGB_STRIDE 132
#define IG_STAGE (128 * IGA_STRIDE + 16 * IGB_STRIDE)   // 4672 floats
#define IG_SMEM_BYTES (3 * IG_STAGE * 4)                // 56064

// ---------------- full software grid barrier (init only) -------------------
__device__ __forceinline__ void grid_barrier() {
    __syncthreads();
    if (threadIdx.x == 0) {
        __threadfence();
        unsigned gen = g_gen;
        if (atomicAdd(&g_count, 1u) == NBLK - 1u) {
            g_count = 0u;
            __threadfence();
            g_gen = gen + 1u;
        } else {
            while (g_gen == gen) {}
        }
        __threadfence();
    }
    __syncthreads();
}

// ---------------- tf32 pre-truncation ---------------------------------------
__global__ void trunc_kernel(const float* __restrict__ in,
                             float* __restrict__ out, int n4)
{
    int i = blockIdx.x * blockDim.x + threadIdx.x;
    if (i < n4) {
        float4 v = ((const float4*)in)[i];
        v.x = to_tf32(v.x); v.y = to_tf32(v.y);
        v.z = to_tf32(v.z); v.w = to_tf32(v.w);
        ((float4*)out)[i] = v;
    }
}

// ---------------------------------------------------------------------------
// Input GEMM v5: round-5 geometry (256 thr, 8 warps 2x4, warp tile 64x32,
// BK=16) + 3-stage cp.async pipeline, one __syncthreads per iteration.
// A and Bt must be pre-truncated tf32.
// REMAP=1: output row r=(t*64+b) <- A row (b*256+t).
// ---------------------------------------------------------------------------
template<int REMAP>
__global__ __launch_bounds__(256) void input_gemm(
    const float* __restrict__ A, const float* __restrict__ Bt,
    float* __restrict__ C, int K)
{
    extern __shared__ __align__(16) float sm[];
    const int tid = threadIdx.x;
    const int wid = tid >> 5;
    const int wr = wid >> 2;        // 0..1
    const int wc = wid & 3;         // 0..3
    const int r0 = blockIdx.y * 128, n0 = blockIdx.x * 128;

    wmma::fragment<wmma::accumulator, 16, 16, 8, float> c[4][2];
#pragma unroll
    for (int i = 0; i < 4; i++)
#pragma unroll
        for (int j = 0; j < 2; j++) wmma::fill_fragment(c[i][j], 0.f);

    // A staging: rows arow0 and arow0+64, 1 float4 each
    const int arow0 = tid >> 2, ak4 = (tid & 3) * 4;
    const int rr0 = r0 + arow0, rr1 = r0 + arow0 + 64;
    const size_t gr0 = REMAP ? ((size_t)(rr0 & 63) * TT + (rr0 >> 6)) : (size_t)rr0;
    const size_t gr1 = REMAP ? ((size_t)(rr1 & 63) * TT + (rr1 >> 6)) : (size_t)rr1;
    const float* aptr0 = A + gr0 * K + ak4;
    const float* aptr1 = A + gr1 * K + ak4;
    const uint32_t dA0 = (uint32_t)(arow0 * IGA_STRIDE + ak4) * 4;
    const uint32_t dA1 = (uint32_t)((arow0 + 64) * IGA_STRIDE + ak4) * 4;
    // B staging: k-rows brow and brow+8, 1 float4 each
    const int brow = tid >> 5, bc4 = (tid & 31) * 4;
    const float* bptr = Bt + (size_t)brow * G4 + n0 + bc4;
    const uint32_t dB0 = (uint32_t)(128 * IGA_STRIDE + brow * IGB_STRIDE + bc4) * 4;
    const uint32_t dB1 = dB0 + 8 * IGB_STRIDE * 4;

    const uint32_t sb = smem_u32(sm);

#define IG_ISSUE(st, k0)                                                      \
    do {                                                                      \
        uint32_t base = sb + (uint32_t)(st) * (IG_STAGE * 4);                 \
        asm volatile("cp.async.cg.shared.global [%0], [%1], 16;"              \
                     :: "r"(base + dA0), "l"(aptr0 + (k0)));                  \
        asm volatile("cp.async.cg.shared.global [%0], [%1], 16;"              \
                     :: "r"(base + dA1), "l"(aptr1 + (k0)));                  \
        asm volatile("cp.async.cg.shared.global [%0], [%1], 16;"              \
                     :: "r"(base + dB0), "l"(bptr + (size_t)(k0) * G4));      \
        asm volatile("cp.async.cg.shared.global [%0], [%1], 16;"              \
                     :: "r"(base + dB1), "l"(bptr + (size_t)((k0) + 8) * G4));\
        asm volatile("cp.async.commit_group;" ::: "memory");                  \
    } while (0)

    IG_ISSUE(0, 0);
    IG_ISSUE(1, 16);

    const int KI = K >> 4;
    for (int kt = 0; kt < KI; kt++) {
        if (kt + 1 < KI)
            asm volatile("cp.async.wait_group 1;" ::: "memory");
        else
            asm volatile("cp.async.wait_group 0;" ::: "memory");
        __syncthreads();
        if (kt + 2 < KI) IG_ISSUE((kt + 2) % 3, (kt + 2) * 16);
        const float* As = sm + (kt % 3) * IG_STAGE;
        const float* Bs = As + 128 * IGA_STRIDE;
#pragma unroll
        for (int kk = 0; kk < 2; kk++) {
            wmma::fragment<wmma::matrix_a, 16, 16, 8, wmma::precision::tf32, wmma::row_major> af[4];
            wmma::fragment<wmma::matrix_b, 16, 16, 8, wmma::precision::tf32, wmma::row_major> bf[2];
#pragma unroll
            for (int i = 0; i < 4; i++)
                wmma::load_matrix_sync(af[i],
                    As + (wr * 64 + i * 16) * IGA_STRIDE + kk * 8, IGA_STRIDE);
#pragma unroll
            for (int j = 0; j < 2; j++)
                wmma::load_matrix_sync(bf[j],
                    Bs + (kk * 8) * IGB_STRIDE + wc * 32 + j * 16, IGB_STRIDE);
#pragma unroll
            for (int i = 0; i < 4; i++)
#pragma unroll
                for (int j = 0; j < 2; j++)
                    wmma::mma_sync(c[i][j], af[i], bf[j], c[i][j]);
        }
    }
#undef IG_ISSUE

#pragma unroll
    for (int i = 0; i < 4; i++)
#pragma unroll
        for (int j = 0; j < 2; j++)
            wmma::store_matrix_sync(
                C + (size_t)(r0 + wr * 64 + i * 16) * G4 + n0 + wc * 32 + j * 16,
                c[i][j], G4, wmma::mem_row_major);
}

// ---------------------------------------------------------------------------
// Persistent recurrent layer (round-13 exact; seq stores tf32 for next GEMM).
// ---------------------------------------------------------------------------
template<bool WRITE_SEQ>
__global__ __launch_bounds__(REC_THR, 1) void lstm_rec(
    const float* __restrict__ xz,
    const float* __restrict__ U,
    const float* __restrict__ bias,
    float* __restrict__ seq_out)
{
    extern __shared__ __align__(16) float smem[];
    float* zsb = smem + ZS_OFF;

    const int tid  = threadIdx.x;
    const int w    = tid >> 5;
    const int lane = tid & 31;
    const int u0   = blockIdx.x * 8;
    const int lq   = lane >> 2;
    const int lr   = lane & 3;

    float breg[128];
#pragma unroll
    for (int c = 0; c < 4; c++)
#pragma unroll
        for (int q = 0; q < 4; q++)
#pragma unroll
            for (int j = 0; j < 4; j++)
#pragma unroll
                for (int r = 0; r < 2; r++) {
                    int kg = c * 256 + w * 32 + q * 8 + r * 4 + lr;
                    breg[((c * 4 + q) * 4 + j) * 2 + r] =
                        to_tf32(__ldg(&U[(size_t)kg * G4 + j * HH + u0 + lq]));
                }

    float creg[2] = {0.f, 0.f};
    float bg[2][4], xzv[2][4];
#pragma unroll
    for (int i = 0; i < 2; i++) {
        int p = tid + i * 256;
        int b = p >> 3, uu = p & 7;
        g_hA[b * HH + u0 + uu] = 0.f;
#pragma unroll
        for (int g = 0; g < 4; g++) {
            bg[i][g]  = __ldg(&bias[g * HH + u0 + uu]);
            xzv[i][g] = __ldcg(&xz[(size_t)b * G4 + g * HH + u0 + uu]);
        }
    }
    grid_barrier();

    const uint32_t sb0 = smem_u32(smem);

    for (int t = 0; t < TT; t++) {
        const float* hp = (t & 1) ? g_hB : g_hA;
        float*       hn = (t & 1) ? g_hA : g_hB;

        float C[4][4][4];
#pragma unroll
        for (int m = 0; m < 4; m++)
#pragma unroll
            for (int j = 0; j < 4; j++)
#pragma unroll
                for (int r = 0; r < 4; r++) C[m][j][r] = 0.f;

#define CP_ISSUE(cc)                                                          \
        do {                                                                  \
            uint32_t dbase = sb0 + ((cc) & 1) * (BUF_FLOATS * 4);             \
            _Pragma("unroll")                                                 \
            for (int it = 0; it < 16; it++) {                                 \
                int idx = tid + it * 256;                                     \
                int row = idx >> 6, qq = idx & 63;                            \
                uint32_t d = dbase + (uint32_t)(row * 260 + qq * 4) * 4;      \
                const float* sgp = hp + (size_t)row * HH + (cc) * 256 + qq * 4; \
                asm volatile("cp.async.cg.shared.global [%0], [%1], 16;"      \
                             :: "r"(d), "l"(sgp));                            \
            }                                                                 \
            asm volatile("cp.async.commit_group;" ::: "memory");              \
        } while (0)

        CP_ISSUE(0);
        CP_ISSUE(1);

#pragma unroll
        for (int c = 0; c < 4; c++) {
            if (c < 3) asm volatile("cp.async.wait_group 1;" ::: "memory");
            else       asm volatile("cp.async.wait_group 0;" ::: "memory");
            __syncthreads();
            const float* bufc = smem + (c & 1) * BUF_FLOATS;
#pragma unroll
            for (int q = 0; q < 4; q++) {
                const int kb = w * 32 + q * 8 + lr;
#pragma unroll
                for (int m = 0; m < 4; m++) {
                    const int r0 = m * 16 + lq;
                    float a0 = bufc[r0 * 260 + kb];
                    float a1 = bufc[(r0 + 8) * 260 + kb];
                    float a2 = bufc[r0 * 260 + kb + 4];
                    float a3 = bufc[(r0 + 8) * 260 + kb + 4];
#pragma unroll
                    for (int j = 0; j < 4; j++)
                        mma_tf32(C[m][j], a0, a1, a2, a3,
                                 breg[((c * 4 + q) * 4 + j) * 2],
                                 breg[((c * 4 + q) * 4 + j) * 2 + 1]);
                }
            }
            if (c < 2) {
                __syncthreads();
                CP_ISSUE(c + 2);
            }
        }
#undef CP_ISSUE

        {
            float* zp = zsb + w * (64 * ZS_STRIDE);
#pragma unroll
            for (int m = 0; m < 4; m++) {
                int r0 = m * 16 + lq;
#pragma unroll
                for (int j = 0; j < 4; j++) {
                    int col = j * 8 + lr * 2;
                    *(float2*)&zp[r0 * ZS_STRIDE + col] =
                        make_float2(C[m][j][0], C[m][j][1]);
                    *(float2*)&zp[(r0 + 8) * ZS_STRIDE + col] =
                        make_float2(C[m][j][2], C[m][j][3]);
                }
            }
        }
        __syncthreads();

#pragma unroll
        for (int i = 0; i < 2; i++) {
            int p = tid + i * 256;
            int b = p >> 3, uu = p & 7;
            float z[4];
#pragma unroll
            for (int g = 0; g < 4; g++) {
                float v = xzv[i][g] + bg[i][g];
#pragma unroll
                for (int pw = 0; pw < 8; pw++)
                    v += zsb[pw * (64 * ZS_STRIDE) + b * ZS_STRIDE + g * 8 + uu];
                z[g] = v;
            }
            float ig = 1.f / (1.f + __expf(-z[0]));
            float fg = 1.f / (1.f + __expf(-z[1]));
            float og = 1.f / (1.f + __expf(-z[3]));
            float cn = fg * creg[i] + ig * tanhf(z[2]);
            float hv = og * tanhf(cn);
            creg[i] = cn;
            float hvt = to_tf32(hv);
            hn[b * HH + u0 + uu] = hvt;
            if (WRITE_SEQ)
                seq_out[((size_t)t * BB + b) * HH + u0 + uu] = hvt;
        }

        __syncthreads();
        unsigned gn0 = 0;
        if (tid == 0) {
            __threadfence();
            gn0 = g_gen;
            if (atomicAdd(&g_count, 1u) == NBLK - 1u) {
                g_count = 0u;
                __threadfence();
                g_gen = gn0 + 1u;
            }
        }
        if (t + 1 < TT) {
#pragma unroll
            for (int i = 0; i < 2; i++) {
                int p = tid + i * 256;
                int b = p >> 3, uu = p & 7;
                const float* xzr = xz + ((size_t)(t + 1) * BB + b) * G4;
#pragma unroll
                for (int g = 0; g < 4; g++)
                    xzv[i][g] = __ldcg(&xzr[g * HH + u0 + uu]);
            }
        }
        if (tid == 0) {
            while (g_gen == gn0) {}
            __threadfence();
        }
        __syncthreads();
    }
}

// ---------------------------------------------------------------------------
__global__ __launch_bounds__(OO) void dense_kernel(
    const float* __restrict__ Wd, const float* __restrict__ bd,
    float* __restrict__ out)
{
    __shared__ float hs[HH];
    int b = blockIdx.x;
    int o = threadIdx.x;
    for (int k = o; k < HH; k += OO) hs[k] = g_hA[(size_t)b * HH + k];
    __syncthreads();
    float acc = 0.f;
#pragma unroll 8
    for (int k = 0; k < HH; k++)
        acc += hs[k] * __ldg(&Wd[(size_t)k * OO + o]);
    out[(size_t)b * OO + o] = acc + bd[o];
}

// ---------------------------------------------------------------------------
extern "C" void kernel_launch(void* const* d_in, const int* in_sizes, int n_in,
                              void* d_out, int out_size)
{
    const float* x  = (const float*)d_in[0];
    const float* W1 = (const float*)d_in[1];
    const float* U1 = (const float*)d_in[2];
    const float* b1 = (const float*)d_in[3];
    const float* W2 = (const float*)d_in[4];
    const float* U2 = (const float*)d_in[5];
    const float* b2 = (const float*)d_in[6];
    const float* Wd = (const float*)d_in[7];
    const float* bd = (const float*)d_in[8];
    float* out = (float*)d_out;

    float *xz, *seq1, *Wt;
    cudaGetSymbolAddress((void**)&xz,   g_xz);
    cudaGetSymbolAddress((void**)&seq1, g_seq1);
    cudaGetSymbolAddress((void**)&Wt,   g_Wt);

    cudaFuncSetAttribute(lstm_rec<true>,
        cudaFuncAttributeMaxDynamicSharedMemorySize, REC_SMEM_BYTES);
    cudaFuncSetAttribute(lstm_rec<false>,
        cudaFuncAttributeMaxDynamicSharedMemorySize, REC_SMEM_BYTES);
    cudaFuncSetAttribute(input_gemm<0>,
        cudaFuncAttributeMaxDynamicSharedMemorySize, IG_SMEM_BYTES);
    cudaFuncSetAttribute(input_gemm<1>,
        cudaFuncAttributeMaxDynamicSharedMemorySize, IG_SMEM_BYTES);

    // ---- layer 1 ----
    trunc_kernel<<<(DD * G4 / 4 + 255) / 256, 256>>>(W1, Wt, DD * G4 / 4);
    trunc_kernel<<<(BB * TT * DD / 4 + 255) / 256, 256>>>(x, seq1, BB * TT * DD / 4);
    input_gemm<1><<<dim3(G4 / 128, MROWS / 128), 256, IG_SMEM_BYTES>>>(seq1, Wt, xz, DD);
    lstm_rec<true><<<NBLK, REC_THR, REC_SMEM_BYTES>>>(xz, U1, b1, seq1);

    // ---- layer 2 ----
    trunc_kernel<<<(HH * G4 / 4 + 255) / 256, 256>>>(W2, Wt, HH * G4 / 4);
    input_gemm<0><<<dim3(G4 / 128, MROWS / 128), 256, IG_SMEM_BYTES>>>(seq1, Wt, xz, HH);
    lstm_rec<false><<<NBLK, REC_THR, REC_SMEM_BYTES>>>(xz, U2, b2, nullptr);

    // ---- dense head ----
    dense_kernel<<<BB, OO>>>(Wd, bd, out);
}

// round 17
// speedup vs baseline: 1.5503x; 1.3576x over previous
#include <cuda_runtime.h>
#include <cuda_fp16.h>
#include <mma.h>
#include <math.h>
#include <stdint.h>
#include <cstdint>

using namespace nvcuda;

#define BB 64
#define TT 256
#define DD 512
#define HH 1024
#define G4 4096
#define OO 512
#define NBLK 128
#define REC_THR 256
#define MROWS (BB*TT)   // 16384

// ---------------- scratch (device globals: allocation-free rule) -----------
__device__ float g_xz[(size_t)MROWS * G4];                    // 256 MB fp32
__device__ __align__(16) __half g_seqh[(size_t)MROWS * HH];   // 32 MB: x-half early, seq later
__device__ __align__(16) __half g_Wh[(size_t)HH * G4];        // 8 MB half W
__device__ __align__(16) __half g_hA[BB * HH];
__device__ __align__(16) __half g_hB[BB * HH];
__device__ unsigned g_count = 0;
__device__ volatile unsigned g_gen = 0;

__device__ __forceinline__ uint32_t smem_u32(const void* p) {
    uint32_t a;
    asm("{ .reg .u64 t; cvta.to.shared.u64 t, %1; cvt.u32.u64 %0, t; }"
        : "=r"(a) : "l"(p));
    return a;
}

// raw fp16 mma m16n8k16, fp32 accumulate
__device__ __forceinline__ void mma_f16(float* c,
    uint32_t a0, uint32_t a1, uint32_t a2, uint32_t a3,
    uint32_t b0, uint32_t b1)
{
    asm volatile(
        "mma.sync.aligned.m16n8k16.row.col.f32.f16.f16.f32 "
        "{%0,%1,%2,%3}, {%4,%5,%6,%7}, {%8,%9}, {%0,%1,%2,%3};"
        : "+f"(c[0]), "+f"(c[1]), "+f"(c[2]), "+f"(c[3])
        : "r"(a0), "r"(a1), "r"(a2), "r"(a3), "r"(b0), "r"(b1));
}

// lstm_rec smem: 2 h-chunk half buffers [64][264] + zs [8][64][40] fp32
#define HBUF_HALFS   (64 * 264)              // 16896 halfs
#define HBUF_BYTES   (HBUF_HALFS * 2)        // 33792
#define ZS_STRIDE    40
#define ZS_BYTE_OFF  (2 * HBUF_BYTES)        // 67584
#define REC_SMEM_BYTES (ZS_BYTE_OFF + 8 * 64 * ZS_STRIDE * 4)   // 149504

// input_gemm fp16 smem: 3 stages of (A 128x24 + B 16x136) halfs
#define IGA_ST 24
#define IGB_ST 136
#define IG_STAGE_H (128 * IGA_ST + 16 * IGB_ST)   // 5248 halfs
#define IG_STAGE_B (IG_STAGE_H * 2)               // 10496 bytes

// ---------------- full software grid barrier (init only) -------------------
__device__ __forceinline__ void grid_barrier() {
    __syncthreads();
    if (threadIdx.x == 0) {
        __threadfence();
        unsigned gen = g_gen;
        if (atomicAdd(&g_count, 1u) == NBLK - 1u) {
            g_count = 0u;
            __threadfence();
            g_gen = gen + 1u;
        } else {
            while (g_gen == gen) {}
        }
        __threadfence();
    }
    __syncthreads();
}

// ---------------- fp32 -> fp16 conversion ----------------------------------
__global__ void f2h_kernel(const float* __restrict__ in,
                           __half* __restrict__ out, int n4)
{
    int i = blockIdx.x * blockDim.x + threadIdx.x;
    if (i < n4) {
        float4 v = ((const float4*)in)[i];
        __half2 a = __floats2half2_rn(v.x, v.y);
        __half2 b = __floats2half2_rn(v.z, v.w);
        uint2 u;
        u.x = *(uint32_t*)&a;
        u.y = *(uint32_t*)&b;
        ((uint2*)out)[i] = u;
    }
}

// ---------------------------------------------------------------------------
// Input GEMM fp16: C[r][n] = A[r][:] @ Bt[:][n], A/Bt half, C fp32.
// 256 thr, 8 warps (2x4), warp tile 64x32, BK=16, 3-stage cp.async,
// one __syncthreads per iteration. REMAP=1: row r=(t*64+b) <- A row (b*256+t).
// ---------------------------------------------------------------------------
template<int REMAP>
__global__ __launch_bounds__(256) void input_gemm(
    const __half* __restrict__ A, const __half* __restrict__ Bt,
    float* __restrict__ C, int K)
{
    __shared__ __align__(16) __half sst[3][IG_STAGE_H];
    const int tid = threadIdx.x;
    const int wid = tid >> 5;
    const int wr = wid >> 2;        // 0..1
    const int wc = wid & 3;         // 0..3
    const int r0 = blockIdx.y * 128, n0 = blockIdx.x * 128;

    wmma::fragment<wmma::accumulator, 16, 16, 16, float> c[4][2];
#pragma unroll
    for (int i = 0; i < 4; i++)
#pragma unroll
        for (int j = 0; j < 2; j++) wmma::fill_fragment(c[i][j], 0.f);

    // A staging: 128 rows x 16 halfs = 2 granules/row; thread -> (row, half)
    const int arow = tid >> 1, ag = tid & 1;
    const int rr = r0 + arow;
    const size_t gr = REMAP ? ((size_t)(rr & 63) * TT + (rr >> 6)) : (size_t)rr;
    const __half* aptr = A + gr * K + ag * 8;
    const uint32_t dA = (uint32_t)(arow * IGA_ST + ag * 8) * 2;
    // B staging: 16 k-rows x 128 halfs = 16 granules/row
    const int brow = tid >> 4, bgq = tid & 15;
    const __half* bptr = Bt + (size_t)brow * G4 + n0 + bgq * 8;
    const uint32_t dB = (uint32_t)(128 * IGA_ST + brow * IGB_ST + bgq * 8) * 2;

    const uint32_t sb = smem_u32(sst);

#define IG_ISSUE(st, k0)                                                      \
    do {                                                                      \
        uint32_t base = sb + (uint32_t)(st) * IG_STAGE_B;                     \
        asm volatile("cp.async.cg.shared.global [%0], [%1], 16;"              \
                     :: "r"(base + dA), "l"(aptr + (k0)));                    \
        asm volatile("cp.async.cg.shared.global [%0], [%1], 16;"              \
                     :: "r"(base + dB), "l"(bptr + (size_t)(k0) * G4));       \
        asm volatile("cp.async.commit_group;" ::: "memory");                  \
    } while (0)

    IG_ISSUE(0, 0);
    IG_ISSUE(1, 16);

    const int KI = K >> 4;
    for (int kt = 0; kt < KI; kt++) {
        if (kt + 1 < KI)
            asm volatile("cp.async.wait_group 1;" ::: "memory");
        else
            asm volatile("cp.async.wait_group 0;" ::: "memory");
        __syncthreads();
        if (kt + 2 < KI) IG_ISSUE((kt + 2) % 3, (kt + 2) * 16);
        const __half* As = sst[kt % 3];
        const __half* Bs = As + 128 * IGA_ST;
        wmma::fragment<wmma::matrix_a, 16, 16, 16, __half, wmma::row_major> af[4];
        wmma::fragment<wmma::matrix_b, 16, 16, 16, __half, wmma::row_major> bf[2];
#pragma unroll
        for (int i = 0; i < 4; i++)
            wmma::load_matrix_sync(af[i], As + (wr * 64 + i * 16) * IGA_ST, IGA_ST);
#pragma unroll
        for (int j = 0; j < 2; j++)
            wmma::load_matrix_sync(bf[j], Bs + wc * 32 + j * 16, IGB_ST);
#pragma unroll
        for (int i = 0; i < 4; i++)
#pragma unroll
            for (int j = 0; j < 2; j++)
                wmma::mma_sync(c[i][j], af[i], bf[j], c[i][j]);
    }
#undef IG_ISSUE

#pragma unroll
    for (int i = 0; i < 4; i++)
#pragma unroll
        for (int j = 0; j < 2; j++)
            wmma::store_matrix_sync(
                C + (size_t)(r0 + wr * 64 + i * 16) * G4 + n0 + wc * 32 + j * 16,
                c[i][j], G4, wmma::mem_row_major);
}

// ---------------------------------------------------------------------------
// Persistent recurrent layer v7 (fp16 m16n8k16).
//   256 threads, 8 warps. U (32 cols x 1024 k) in registers as 64 packed
//   half2 b-frags. h (half) staged via cp.async in 4 x 32KB chunks,
//   double-buffered. Warp w covers k-range [w*32, w*32+32) of each chunk.
// ---------------------------------------------------------------------------
template<bool WRITE_SEQ>
__global__ __launch_bounds__(REC_THR, 1) void lstm_rec(
    const float* __restrict__ xz,   // [t*64+b][4096] fp32
    const float* __restrict__ U,    // [1024][4096] fp32
    const float* __restrict__ bias, // [4096]
    __half* __restrict__ seq_out)   // [t*64+b][1024] half or null
{
    extern __shared__ __align__(16) char smc[];
    float* zsb = (float*)(smc + ZS_BYTE_OFF);   // [8][64][40]

    const int tid  = threadIdx.x;
    const int w    = tid >> 5;
    const int lane = tid & 31;
    const int u0   = blockIdx.x * 8;
    const int lq   = lane >> 2;     // 0..7
    const int lr   = lane & 3;      // 0..3

    // ---- one-time: pack U b-fragments into registers (half2) -------------
    uint32_t breg[64];   // index ((c*2+q)*4 + j)*2 + r
#pragma unroll
    for (int c = 0; c < 4; c++)
#pragma unroll
        for (int q = 0; q < 2; q++)
#pragma unroll
            for (int j = 0; j < 4; j++)
#pragma unroll
                for (int r = 0; r < 2; r++) {
                    int kg = c * 256 + w * 32 + q * 16 + lr * 2 + r * 8;
                    int col = j * HH + u0 + lq;
                    float v0 = __ldg(&U[(size_t)kg * G4 + col]);
                    float v1 = __ldg(&U[(size_t)(kg + 1) * G4 + col]);
                    __half2 p = __floats2half2_rn(v0, v1);
                    breg[((c * 2 + q) * 4 + j) * 2 + r] = *(uint32_t*)&p;
                }

    // ---- gate state: 2 (b,unit) pairs per thread -------------------------
    float creg[2] = {0.f, 0.f};
    float bg[2][4], xzv[2][4];
#pragma unroll
    for (int i = 0; i < 2; i++) {
        int p = tid + i * 256;
        int b = p >> 3, uu = p & 7;
        g_hA[b * HH + u0 + uu] = __float2half(0.f);
#pragma unroll
        for (int g = 0; g < 4; g++) {
            bg[i][g]  = __ldg(&bias[g * HH + u0 + uu]);
            xzv[i][g] = __ldcg(&xz[(size_t)b * G4 + g * HH + u0 + uu]);
        }
    }
    grid_barrier();

    const uint32_t sb0 = smem_u32(smc);

    for (int t = 0; t < TT; t++) {
        const __half* hp = (t & 1) ? g_hB : g_hA;
        __half*       hn = (t & 1) ? g_hA : g_hB;

        float C[4][4][4];
#pragma unroll
        for (int m = 0; m < 4; m++)
#pragma unroll
            for (int j = 0; j < 4; j++)
#pragma unroll
                for (int r = 0; r < 4; r++) C[m][j][r] = 0.f;

        // stage one chunk: 64 rows x 256 halfs = 2048 granules, 8/thread
#define CP_ISSUE(cc)                                                          \
        do {                                                                  \
            uint32_t dbase = sb0 + ((cc) & 1) * HBUF_BYTES;                   \
            _Pragma("unroll")                                                 \
            for (int it = 0; it < 8; it++) {                                  \
                int idx = tid + it * 256;                                     \
                int row = idx >> 5, qq = idx & 31;                            \
                uint32_t d = dbase + (uint32_t)(row * 528 + qq * 16);         \
                const __half* sgp = hp + (size_t)row * HH + (cc) * 256 + qq * 8; \
                asm volatile("cp.async.cg.shared.global [%0], [%1], 16;"      \
                             :: "r"(d), "l"(sgp));                            \
            }                                                                 \
            asm volatile("cp.async.commit_group;" ::: "memory");              \
        } while (0)

        CP_ISSUE(0);
        CP_ISSUE(1);

#pragma unroll
        for (int c = 0; c < 4; c++) {
            if (c < 3) asm volatile("cp.async.wait_group 1;" ::: "memory");
            else       asm volatile("cp.async.wait_group 0;" ::: "memory");
            __syncthreads();
            const __half* bufc = (const __half*)(smc + (c & 1) * HBUF_BYTES);
#pragma unroll
            for (int q = 0; q < 2; q++) {
                const int kb = w * 32 + q * 16 + lr * 2;
#pragma unroll
                for (int m = 0; m < 4; m++) {
                    const int r0 = m * 16 + lq;
                    uint32_t a0 = *(const uint32_t*)&bufc[r0 * 264 + kb];
                    uint32_t a1 = *(const uint32_t*)&bufc[(r0 + 8) * 264 + kb];
                    uint32_t a2 = *(const uint32_t*)&bufc[r0 * 264 + kb + 8];
                    uint32_t a3 = *(const uint32_t*)&bufc[(r0 + 8) * 264 + kb + 8];
#pragma unroll
                    for (int j = 0; j < 4; j++)
                        mma_f16(C[m][j], a0, a1, a2, a3,
                                breg[((c * 2 + q) * 4 + j) * 2],
                                breg[((c * 2 + q) * 4 + j) * 2 + 1]);
                }
            }
            if (c < 2) {
                __syncthreads();
                CP_ISSUE(c + 2);
            }
        }
#undef CP_ISSUE

        // ---- epilogue: C -> zs partials ----------------------------------
        {
            float* zp = zsb + w * (64 * ZS_STRIDE);
#pragma unroll
            for (int m = 0; m < 4; m++) {
                int r0 = m * 16 + lq;
#pragma unroll
                for (int j = 0; j < 4; j++) {
                    int col = j * 8 + lr * 2;
                    *(float2*)&zp[r0 * ZS_STRIDE + col] =
                        make_float2(C[m][j][0], C[m][j][1]);
                    *(float2*)&zp[(r0 + 8) * ZS_STRIDE + col] =
                        make_float2(C[m][j][2], C[m][j][3]);
                }
            }
        }
        __syncthreads();

        // ---- fused gates (2 pairs per thread) ----------------------------
#pragma unroll
        for (int i = 0; i < 2; i++) {
            int p = tid + i * 256;
            int b = p >> 3, uu = p & 7;
            float z[4];
#pragma unroll
            for (int g = 0; g < 4; g++) {
                float v = xzv[i][g] + bg[i][g];
#pragma unroll
                for (int pw = 0; pw < 8; pw++)
                    v += zsb[pw * (64 * ZS_STRIDE) + b * ZS_STRIDE + g * 8 + uu];
                z[g] = v;
            }
            float ig = 1.f / (1.f + __expf(-z[0]));
            float fg = 1.f / (1.f + __expf(-z[1]));
            float og = 1.f / (1.f + __expf(-z[3]));
            float cn = fg * creg[i] + ig * tanhf(z[2]);
            float hv = og * tanhf(cn);
            creg[i] = cn;
            __half hh = __float2half_rn(hv);
            hn[b * HH + u0 + uu] = hh;
            if (WRITE_SEQ)
                seq_out[((size_t)t * BB + b) * HH + u0 + uu] = hh;
        }

        // ---- split-phase grid barrier with xz prefetch overlap -----------
        __syncthreads();
        unsigned gn0 = 0;
        if (tid == 0) {
            __threadfence();
            gn0 = g_gen;
            if (atomicAdd(&g_count, 1u) == NBLK - 1u) {
                g_count = 0u;
                __threadfence();
                g_gen = gn0 + 1u;
            }
        }
        if (t + 1 < TT) {
#pragma unroll
            for (int i = 0; i < 2; i++) {
                int p = tid + i * 256;
                int b = p >> 3, uu = p & 7;
                const float* xzr = xz + ((size_t)(t + 1) * BB + b) * G4;
#pragma unroll
                for (int g = 0; g < 4; g++)
                    xzv[i][g] = __ldcg(&xzr[g * HH + u0 + uu]);
            }
        }
        if (tid == 0) {
            while (g_gen == gn0) {}
            __threadfence();
        }
        __syncthreads();
    }
}

// ---------------------------------------------------------------------------
// Final dense: out[b][o] = h_final[b][:] . Wd[:,o] + bd[o]  (h_final = g_hA)
// ---------------------------------------------------------------------------
__global__ __launch_bounds__(OO) void dense_kernel(
    const float* __restrict__ Wd, const float* __restrict__ bd,
    float* __restrict__ out)
{
    __shared__ float hs[HH];
    int b = blockIdx.x;
    int o = threadIdx.x;
    for (int k = o; k < HH; k += OO) hs[k] = __half2float(g_hA[(size_t)b * HH + k]);
    __syncthreads();
    float acc = 0.f;
#pragma unroll 8
    for (int k = 0; k < HH; k++)
        acc += hs[k] * __ldg(&Wd[(size_t)k * OO + o]);
    out[(size_t)b * OO + o] = acc + bd[o];
}

// ---------------------------------------------------------------------------
extern "C" void kernel_launch(void* const* d_in, const int* in_sizes, int n_in,
                              void* d_out, int out_size)
{
    const float* x  = (const float*)d_in[0];
    const float* W1 = (const float*)d_in[1];
    const float* U1 = (const float*)d_in[2];
    const float* b1 = (const float*)d_in[3];
    const float* W2 = (const float*)d_in[4];
    const float* U2 = (const float*)d_in[5];
    const float* b2 = (const float*)d_in[6];
    const float* Wd = (const float*)d_in[7];
    const float* bd = (const float*)d_in[8];
    float* out = (float*)d_out;

    float* xz;
    __half *seqh, *Wh;
    cudaGetSymbolAddress((void**)&xz,   g_xz);
    cudaGetSymbolAddress((void**)&seqh, g_seqh);
    cudaGetSymbolAddress((void**)&Wh,   g_Wh);

    cudaFuncSetAttribute(lstm_rec<true>,
        cudaFuncAttributeMaxDynamicSharedMemorySize, REC_SMEM_BYTES);
    cudaFuncSetAttribute(lstm_rec<false>,
        cudaFuncAttributeMaxDynamicSharedMemorySize, REC_SMEM_BYTES);

    // ---- layer 1 ----
    f2h_kernel<<<(DD * G4 / 4 + 255) / 256, 256>>>(W1, Wh, DD * G4 / 4);
    f2h_kernel<<<(BB * TT * DD / 4 + 255) / 256, 256>>>(x, seqh, BB * TT * DD / 4);
    input_gemm<1><<<dim3(G4 / 128, MROWS / 128), 256>>>(seqh, Wh, xz, DD);
    lstm_rec<true><<<NBLK, REC_THR, REC_SMEM_BYTES>>>(xz, U1, b1, seqh);

    // ---- layer 2 ----
    f2h_kernel<<<(HH * G4 / 4 + 255) / 256, 256>>>(W2, Wh, HH * G4 / 4);
    input_gemm<0><<<dim3(G4 / 128, MROWS / 128), 256>>>(seqh, Wh, xz, HH);
    lstm_rec<false><<<NBLK, REC_THR, REC_SMEM_BYTES>>>(xz, U2, b2, nullptr);

    // ---- dense head ----
    dense_kernel<<<BB, OO>>>(Wd, bd, out);
}